// round 1
// baseline (speedup 1.0000x reference)
#include <cuda_runtime.h>
#include <cuda_bf16.h>
#include <cstdint>

// Problem shapes (fixed by the dataset):
//   x:       [N=4096, I=4096]  float32
//   qweight: [I, O/8=1376]     int32 (8 x int4 nibbles packed along O)
//   scales:  [G=32, O=11008]   float32
//   qzeros:  [G, O/8]          int32 (8 x int4 nibbles)
//   out:     [N, O]            float32
//   group_size = 128, G = I/128

#define BM 128
#define BN 128
#define BK 16
#define THREADS 256
// Each thread computes an 8x8 micro-tile, split as 2x2 blocks of 4x4
// (rows {ty*4 .. +3} and {64+ty*4 .. +3}, cols {tx*4 .. +3} and {64+tx*4 .. +3})
// so shared-memory fragment reads are float4 and conflict-free.

#define AS_STRIDE (BM + 4)
#define BS_STRIDE (BN + 4)

__global__ __launch_bounds__(THREADS, 2)
void q4_gemm_kernel(const float* __restrict__ x,
                    const int*   __restrict__ qweight,
                    const float* __restrict__ scales,
                    const int*   __restrict__ qzeros,
                    float*       __restrict__ out,
                    int N, int I, int O) {
    __shared__ float As[BK][AS_STRIDE];   // x tile, stored transposed: As[k][m]
    __shared__ float Bs[BK][BS_STRIDE];   // dequantized W tile: Bs[k][n]

    const int tid = threadIdx.x;
    const int tx  = tid & 15;   // 0..15  (column group)
    const int ty  = tid >> 4;   // 0..15  (row group)

    const int row0 = blockIdx.y * BM;   // along N
    const int col0 = blockIdx.x * BN;   // along O

    const int Opack = O >> 3;           // O/8

    // B loader mapping: 256 int32 words per tile (BK * BN/8 = 16*16)
    const int b_krow = tid >> 4;        // 0..15 : k-row within tile
    const int b_oc8  = tid & 15;        // 0..15 : which 8-col chunk

    float acc[8][8];
#pragma unroll
    for (int m = 0; m < 8; m++)
#pragma unroll
        for (int n = 0; n < 8; n++) acc[m][n] = 0.0f;

    for (int k0 = 0; k0 < I; k0 += BK) {
        // ---- load x tile [BM x BK], store transposed into As ----
#pragma unroll
        for (int l = 0; l < 2; l++) {
            int q  = tid + l * THREADS;     // 0..511
            int r  = q >> 2;                // 0..127 row within tile
            int c4 = q & 3;                 // which float4 within the BK=16 row
            float4 v = *reinterpret_cast<const float4*>(
                &x[(size_t)(row0 + r) * I + k0 + c4 * 4]);
            As[c4 * 4 + 0][r] = v.x;
            As[c4 * 4 + 1][r] = v.y;
            As[c4 * 4 + 2][r] = v.z;
            As[c4 * 4 + 3][r] = v.w;
        }

        // ---- load + dequant W tile [BK x BN] ----
        {
            const int i = k0 + b_krow;          // global k row
            const int g = i >> 7;               // group (group_size = 128)
            const int opack = (col0 >> 3) + b_oc8;
            const unsigned w = (unsigned)qweight[(size_t)i * Opack + opack];
            const unsigned z = (unsigned)qzeros[(size_t)g * Opack + opack];
            const float* sc = &scales[(size_t)g * O + col0 + b_oc8 * 8];
#pragma unroll
            for (int j = 0; j < 8; j++) {
                int wn = (w >> (4 * j)) & 0xF;
                int zn = (z >> (4 * j)) & 0xF;
                Bs[b_krow][b_oc8 * 8 + j] = (float)(wn - zn) * sc[j];
            }
        }
        __syncthreads();

        // ---- compute ----
#pragma unroll
        for (int kk = 0; kk < BK; kk++) {
            float a[8], b[8];
            float4 a0 = *reinterpret_cast<const float4*>(&As[kk][ty * 4]);
            float4 a1 = *reinterpret_cast<const float4*>(&As[kk][64 + ty * 4]);
            float4 b0 = *reinterpret_cast<const float4*>(&Bs[kk][tx * 4]);
            float4 b1 = *reinterpret_cast<const float4*>(&Bs[kk][64 + tx * 4]);
            a[0]=a0.x; a[1]=a0.y; a[2]=a0.z; a[3]=a0.w;
            a[4]=a1.x; a[5]=a1.y; a[6]=a1.z; a[7]=a1.w;
            b[0]=b0.x; b[1]=b0.y; b[2]=b0.z; b[3]=b0.w;
            b[4]=b1.x; b[5]=b1.y; b[6]=b1.z; b[7]=b1.w;
#pragma unroll
            for (int m = 0; m < 8; m++)
#pragma unroll
                for (int n = 0; n < 8; n++)
                    acc[m][n] = fmaf(a[m], b[n], acc[m][n]);
        }
        __syncthreads();
    }

    // ---- store 8x8 micro-tile (2x2 blocks of 4x4, each row a float4 pair) ----
#pragma unroll
    for (int mb = 0; mb < 2; mb++) {
#pragma unroll
        for (int m = 0; m < 4; m++) {
            int r = row0 + mb * 64 + ty * 4 + m;
            float* orow = &out[(size_t)r * O + col0];
            float4 v0 = make_float4(acc[mb*4+m][0], acc[mb*4+m][1],
                                    acc[mb*4+m][2], acc[mb*4+m][3]);
            float4 v1 = make_float4(acc[mb*4+m][4], acc[mb*4+m][5],
                                    acc[mb*4+m][6], acc[mb*4+m][7]);
            *reinterpret_cast<float4*>(&orow[tx * 4])      = v0;
            *reinterpret_cast<float4*>(&orow[64 + tx * 4]) = v1;
        }
    }
}

extern "C" void kernel_launch(void* const* d_in, const int* in_sizes, int n_in,
                              void* d_out, int out_size) {
    const float* x       = (const float*)d_in[0];
    const int*   qweight = (const int*)d_in[1];
    const float* scales  = (const float*)d_in[2];
    const int*   qzeros  = (const int*)d_in[3];
    float*       out     = (float*)d_out;

    const int I = 4096;
    const int O = 11008;
    const int N = in_sizes[0] / I;   // 4096

    dim3 grid(O / BN, N / BM);       // (86, 32)
    dim3 block(THREADS);
    q4_gemm_kernel<<<grid, block>>>(x, qweight, scales, qzeros, out, N, I, O);
}

// round 4
// speedup vs baseline: 3.0423x; 3.0423x over previous
#include <cuda_runtime.h>
#include <cstdint>

// x:[4096,4096] f32, qweight:[4096,1376] i32 (8x int4 along O), scales:[32,11008] f32,
// qzeros:[32,1376] i32, out:[4096,11008] f32, group_size=128.
// tf32 mma.sync GEMM (tcgen05 rejected by this toolchain's sm_103 target).

#define I_DIM 4096
#define O_DIM 11008
#define OPACK 1376
#define BM 128
#define BN 256
#define BK 32
#define NITER (I_DIM / BK)   // 128
#define THREADS 256

#define A_WORDS (BM * BK)                 // 4096
#define B_WORDS (BN * BK)                 // 8192
#define STAGE_WORDS (A_WORDS + B_WORDS)   // 12288
#define SMEM_BYTES (2 * STAGE_WORDS * 4)  // 98304

__device__ __forceinline__ uint32_t f2tf32(float f) {
    uint32_t u;
    asm("cvt.rna.tf32.f32 %0, %1;" : "=r"(u) : "f"(f));
    return u;
}

__device__ __forceinline__ void mma_tf32(float* d, const uint32_t* a, const uint32_t* b) {
    asm volatile(
        "mma.sync.aligned.m16n8k8.row.col.f32.tf32.tf32.f32 "
        "{%0,%1,%2,%3},{%4,%5,%6,%7},{%8,%9},{%0,%1,%2,%3};"
        : "+f"(d[0]), "+f"(d[1]), "+f"(d[2]), "+f"(d[3])
        : "r"(a[0]), "r"(a[1]), "r"(a[2]), "r"(a[3]), "r"(b[0]), "r"(b[1]));
}

__global__ __launch_bounds__(THREADS, 1)
void q4_tf32_mma(const float* __restrict__ x,
                 const int* __restrict__ qweight,
                 const float* __restrict__ scales,
                 const int* __restrict__ qzeros,
                 float* __restrict__ out) {
    extern __shared__ uint32_t smem[];

    const int tid  = threadIdx.x;
    const int lane = tid & 31;
    const int wid  = tid >> 5;
    const int gi   = lane >> 2;   // 0..7
    const int tq   = lane & 3;    // 0..3

    const int row0 = blockIdx.y * BM;
    const int col0 = blockIdx.x * BN;

    // warp grid: 2 (M) x 4 (N); warp tile 64x64
    const int wm = wid & 1;
    const int wn = wid >> 1;

    const int ow = tid & 31;
    const int kq = tid >> 5;
    const int*   qw_base = qweight + (col0 >> 3) + ow;
    const int*   qz_base = qzeros  + (col0 >> 3) + ow;
    const float* sc_base = scales  + col0 + ow * 8;

    float4   aS[4];
    uint32_t wS[4];
    uint32_t zS;
    float4   sS0, sS1;

    float acc[4][8][4];
#pragma unroll
    for (int mi = 0; mi < 4; mi++)
#pragma unroll
        for (int nb = 0; nb < 8; nb++)
#pragma unroll
            for (int j = 0; j < 4; j++) acc[mi][nb][j] = 0.0f;

    auto load_tile = [&](int it) {
        const int k0 = it * BK;
#pragma unroll
        for (int jj = 0; jj < 4; jj++) {
            int q = jj * 256 + tid;
            int ar = q >> 3;
            int af4 = q & 7;
            aS[jj] = *reinterpret_cast<const float4*>(
                x + (size_t)(row0 + ar) * I_DIM + k0 + af4 * 4);
        }
        const int g = it >> 2;   // group index (BK=32, group=128)
#pragma unroll
        for (int j = 0; j < 4; j++)
            wS[j] = (uint32_t)qw_base[(size_t)(k0 + kq * 4 + j) * OPACK];
        zS  = (uint32_t)qz_base[(size_t)g * OPACK];
        sS0 = *reinterpret_cast<const float4*>(sc_base + (size_t)g * O_DIM);
        sS1 = *reinterpret_cast<const float4*>(sc_base + (size_t)g * O_DIM + 4);
    };

    auto store_tile = [&](int stage) {
        uint32_t* As = smem + stage * STAGE_WORDS;
        uint32_t* Bs = As + A_WORDS;
        // A: word(r,k) = r*32 + ((k>>2)^(r&7))*4 + (k&3)
#pragma unroll
        for (int jj = 0; jj < 4; jj++) {
            int q = jj * 256 + tid;
            int ar = q >> 3;
            int af4 = q & 7;
            uint32_t w = ar * 32 + ((af4 ^ (ar & 7)) << 2);
            uint4 v;
            v.x = f2tf32(aS[jj].x); v.y = f2tf32(aS[jj].y);
            v.z = f2tf32(aS[jj].z); v.w = f2tf32(aS[jj].w);
            *reinterpret_cast<uint4*>(As + w) = v;
        }
        // B: word(n,k) = n*32 + ((k>>2)^((n&7)^((n>>3)&7)))*4 + (k&3)
        float sc[8] = {sS0.x, sS0.y, sS0.z, sS0.w, sS1.x, sS1.y, sS1.z, sS1.w};
#pragma unroll
        for (int o = 0; o < 8; o++) {
            // EXACT dequant: (magic_w - magic_z) is an exact integer difference;
            // folding the 2^23 offset into an FMA loses ~5e-3 absolute (round-3 bug).
            float fz = __uint_as_float(0x4B000000u | ((zS >> (4 * o)) & 0xF));
            uint4 v;
            float f;
            f = __uint_as_float(0x4B000000u | ((wS[0] >> (4 * o)) & 0xF)); v.x = f2tf32((f - fz) * sc[o]);
            f = __uint_as_float(0x4B000000u | ((wS[1] >> (4 * o)) & 0xF)); v.y = f2tf32((f - fz) * sc[o]);
            f = __uint_as_float(0x4B000000u | ((wS[2] >> (4 * o)) & 0xF)); v.z = f2tf32((f - fz) * sc[o]);
            f = __uint_as_float(0x4B000000u | ((wS[3] >> (4 * o)) & 0xF)); v.w = f2tf32((f - fz) * sc[o]);
            int n = ow * 8 + o;
            uint32_t w = n * 32 + ((kq ^ (o ^ (ow & 7))) << 2);
            *reinterpret_cast<uint4*>(Bs + w) = v;
        }
    };

    auto compute = [&](int stage) {
        const uint32_t* As = smem + stage * STAGE_WORDS;
        const uint32_t* Bs = As + A_WORDS;
#pragma unroll
        for (int kb = 0; kb < 4; kb++) {
            uint32_t a[4][4];
#pragma unroll
            for (int mi = 0; mi < 4; mi++) {
                uint32_t base = (wm * 64 + mi * 16 + gi) * 32 + (((2 * kb) ^ gi) << 2) + tq;
                a[mi][0] = As[base];
                a[mi][1] = As[base + 256];
                a[mi][2] = As[base ^ 4];
                a[mi][3] = As[(base ^ 4) + 256];
            }
            uint32_t b[8][2];
#pragma unroll
            for (int nb = 0; nb < 8; nb++) {
                uint32_t base = (wn * 64 + nb * 8 + gi) * 32 + (((2 * kb) ^ (gi ^ nb)) << 2) + tq;
                b[nb][0] = Bs[base];
                b[nb][1] = Bs[base ^ 4];
            }
#pragma unroll
            for (int mi = 0; mi < 4; mi++)
#pragma unroll
                for (int nb = 0; nb < 8; nb++)
                    mma_tf32(acc[mi][nb], a[mi], b[nb]);
        }
    };

    load_tile(0);
    store_tile(0);
    __syncthreads();

    for (int it = 0; it < NITER; ++it) {
        if (it + 1 < NITER) load_tile(it + 1);
        compute(it & 1);
        if (it + 1 < NITER) store_tile((it + 1) & 1);
        __syncthreads();
    }

#pragma unroll
    for (int mi = 0; mi < 4; mi++) {
        int r = row0 + wm * 64 + mi * 16 + gi;
        float* o0 = out + (size_t)r * O_DIM + col0 + wn * 64;
        float* o1 = o0 + 8 * O_DIM;
#pragma unroll
        for (int nb = 0; nb < 8; nb++) {
            int c = nb * 8 + 2 * tq;
            *reinterpret_cast<float2*>(o0 + c) = make_float2(acc[mi][nb][0], acc[mi][nb][1]);
            *reinterpret_cast<float2*>(o1 + c) = make_float2(acc[mi][nb][2], acc[mi][nb][3]);
        }
    }
}

extern "C" void kernel_launch(void* const* d_in, const int* in_sizes, int n_in,
                              void* d_out, int out_size) {
    const float* x       = (const float*)d_in[0];
    const int*   qweight = (const int*)d_in[1];
    const float* scales  = (const float*)d_in[2];
    const int*   qzeros  = (const int*)d_in[3];
    float*       out     = (float*)d_out;

    static int configured = 0;
    if (!configured) {
        cudaFuncSetAttribute(q4_tf32_mma, cudaFuncAttributeMaxDynamicSharedMemorySize, SMEM_BYTES);
        configured = 1;
    }

    dim3 grid(O_DIM / BN, 4096 / BM);   // (43, 32)
    q4_tf32_mma<<<grid, THREADS, SMEM_BYTES>>>(x, qweight, scales, qzeros, out);
}